// round 1
// baseline (speedup 1.0000x reference)
#include <cuda_runtime.h>

#define MROWS 10000
#define KDIM  256
#define NF    64
#define N1R   8192
#define KH    5

// scratch for edge_4att = x @ weight  (allocation-free: __device__ global)
__device__ float g_e4a[MROWS * NF];

// ---------------------------------------------------------------------------
// Kernel 1: e4a = x @ W   (M=10000, K=256, N=64, fp32)
// Block: 256 threads, tile BM=64 rows x BN=64 cols, BK=32.
// Thread microtile: 4 rows x 4 cols (16 accumulators).
// ---------------------------------------------------------------------------
__global__ __launch_bounds__(256) void gemm_kernel(const float* __restrict__ x,
                                                   const float* __restrict__ w) {
    __shared__ float xs[64][36];   // padded to avoid bank conflicts
    __shared__ float ws[32][64];

    const int tid  = threadIdx.x;
    const int row0 = blockIdx.x * 64;
    const int cg   = tid & 15;     // column group: cols cg*4 .. cg*4+3
    const int rg   = tid >> 4;     // row group:    rows rg*4 .. rg*4+3

    float acc[4][4] = {};

    for (int k0 = 0; k0 < KDIM; k0 += 32) {
        // cooperative load of x chunk [64 x 32] and w chunk [32 x 64]
        #pragma unroll
        for (int j = 0; j < 2; j++) {
            int f = tid + j * 256;            // 0..511
            int r = f >> 3, c = f & 7;        // x: 64 rows x 8 float4
            float4 v = make_float4(0.f, 0.f, 0.f, 0.f);
            if (row0 + r < MROWS)
                v = *(const float4*)(x + (size_t)(row0 + r) * KDIM + k0 + c * 4);
            *(float4*)&xs[r][c * 4] = v;

            int kk = f >> 4, wc = f & 15;     // w: 32 k x 16 float4
            *(float4*)&ws[kk][wc * 4] =
                *(const float4*)(w + (size_t)(k0 + kk) * NF + wc * 4);
        }
        __syncthreads();

        #pragma unroll
        for (int kk = 0; kk < 32; kk++) {
            float4 wv = *(const float4*)&ws[kk][cg * 4];
            #pragma unroll
            for (int m = 0; m < 4; m++) {
                float xv = xs[rg * 4 + m][kk];
                acc[m][0] += xv * wv.x;
                acc[m][1] += xv * wv.y;
                acc[m][2] += xv * wv.z;
                acc[m][3] += xv * wv.w;
            }
        }
        __syncthreads();
    }

    #pragma unroll
    for (int m = 0; m < 4; m++) {
        int row = row0 + rg * 4 + m;
        if (row < MROWS) {
            *(float4*)(g_e4a + (size_t)row * NF + cg * 4) =
                make_float4(acc[m][0], acc[m][1], acc[m][2], acc[m][3]);
        }
    }
}

// ---------------------------------------------------------------------------
// Kernel 2: out[i,:] = sum_{k<5} e4a[qq[5i+k], :] + 5*bias
// (floor(softmax/1000) == 0 identically, so e == G exactly.)
// 16 threads per output row, one float4 (4 cols) each. 16 rows per block.
// ---------------------------------------------------------------------------
__global__ __launch_bounds__(256) void gather_kernel(const int* __restrict__ qq,
                                                     const float* __restrict__ bias,
                                                     float* __restrict__ out) {
    const int tid = threadIdx.x;
    const int lr  = tid >> 4;          // local row 0..15
    const int cg  = tid & 15;          // float4 column group 0..15
    const int i   = blockIdx.x * 16 + lr;
    if (i >= N1R) return;

    const int* q = qq + i * KH;
    const float4* e4 = (const float4*)g_e4a;

    float4 b  = ((const float4*)bias)[cg];
    float4 a0 = e4[(size_t)q[0] * 16 + cg];
    float4 a1 = e4[(size_t)q[1] * 16 + cg];
    float4 a2 = e4[(size_t)q[2] * 16 + cg];
    float4 a3 = e4[(size_t)q[3] * 16 + cg];
    float4 a4 = e4[(size_t)q[4] * 16 + cg];

    float4 r;
    r.x = a0.x + a1.x + a2.x + a3.x + a4.x + 5.0f * b.x;
    r.y = a0.y + a1.y + a2.y + a3.y + a4.y + 5.0f * b.y;
    r.z = a0.z + a1.z + a2.z + a3.z + a4.z + 5.0f * b.z;
    r.w = a0.w + a1.w + a2.w + a3.w + a4.w + 5.0f * b.w;

    ((float4*)out)[(size_t)i * 16 + cg] = r;
}

// ---------------------------------------------------------------------------
// Inputs (metadata order = setup_inputs dict order):
//   0: x      [10000,256] f32   (2,560,000)
//   1: G      [8192,10000] f32  (unused)
//   2: weight [256,64] f32      (16,384)
//   3: a      [320,1] f32       (unused — attention branch is identically 0)
//   4: bias   [64] f32
//   5: qq     [40960] i32
//   6: rows   [40960] i32       (unused)
// output: [8192,64] f32
// ---------------------------------------------------------------------------
extern "C" void kernel_launch(void* const* d_in, const int* in_sizes, int n_in,
                              void* d_out, int out_size) {
    const float* x    = (const float*)d_in[0];
    const float* w    = (const float*)d_in[2];
    const float* bias = (const float*)d_in[4];
    const int*   qq   = (const int*)d_in[5];
    float*       out  = (float*)d_out;

    gemm_kernel<<<(MROWS + 63) / 64, 256>>>(x, w);
    gather_kernel<<<N1R / 16, 256>>>(qq, bias, out);
}